// round 6
// baseline (speedup 1.0000x reference)
#include <cuda_runtime.h>
#include <cuda_fp16.h>
#include <cstdint>

// Problem constants
#define N_TOK 262144
#define DIM   64
#define KCB   512
#define GAMMA 0.99f

#define TPB     512
#define TOK_CTA 512
#define NCTA    (N_TOK / TOK_CTA)
#define MARGIN  5e-4f    // >= ~15x worst-case fp16-split coarse error

// smem: codebook hi | mid (SW128-swizzled fp16) | bias fp32 | cn scratch
#define SM_B_HI   0
#define SM_B_MID  65536
#define SM_BIAS   131072
#define SMEM_BYTES (SM_BIAS + 4096)

#define SW(o) ((o) ^ (((o) >> 3) & 0x70))

// device globals (allocation-free; zero-init at load, self-rezeroing each call)
__device__ float g_cs[KCB * DIM];
__device__ float g_cn[KCB];
__device__ unsigned int g_done;

// ---------------- helpers ----------------
__device__ __forceinline__ uint32_t smem_u32(const void* p) {
    uint32_t a;
    asm("{ .reg .u64 t; cvta.to.shared.u64 t, %1; cvt.u32.u64 %0, t; }" : "=r"(a) : "l"(p));
    return a;
}
__device__ __forceinline__ void split2h(float a, float b, uint32_t& h, uint32_t& m) {
    __half2 hh = __floats2half2_rn(a, b);
    float2 bk = __half22float2(hh);
    __half2 mm = __floats2half2_rn(a - bk.x, b - bk.y);
    h = *reinterpret_cast<uint32_t*>(&hh);
    m = *reinterpret_cast<uint32_t*>(&mm);
}

#define LDMX4(R, A) \
    asm volatile("ldmatrix.sync.aligned.m8n8.x4.shared.b16 {%0,%1,%2,%3}, [%4];" \
                 : "=r"((R)[0]), "=r"((R)[1]), "=r"((R)[2]), "=r"((R)[3]) : "r"(A))

#define MMA(C, A, B0, B1) \
    asm volatile("mma.sync.aligned.m16n8k16.row.col.f32.f16.f16.f32 " \
                 "{%0,%1,%2,%3}, {%4,%5,%6,%7}, {%8,%9}, {%0,%1,%2,%3};" \
                 : "+f"((C)[0]), "+f"((C)[1]), "+f"((C)[2]), "+f"((C)[3]) \
                 : "r"((A)[0]), "r"((A)[1]), "r"((A)[2]), "r"((A)[3]), "r"(B0), "r"(B1))

__device__ __forceinline__ void upd(float v, int kk, float& best, float& second, int& bk) {
    if (v > best) { second = best; best = v; bk = kk; }
    else          { second = fmaxf(second, v); }
}

// rare path: exact fp32 rescan of all 512 codewords (kept out of hot regs)
__device__ __noinline__ int rescue(const float* __restrict__ x,
                                   const float* __restrict__ vq,
                                   const float* sbias, int tok) {
    float xr[DIM];
    const float4* xp = reinterpret_cast<const float4*>(x + (size_t)tok * DIM);
    #pragma unroll
    for (int i = 0; i < DIM / 4; i++) {
        float4 t = xp[i];
        xr[4 * i] = t.x; xr[4 * i + 1] = t.y; xr[4 * i + 2] = t.z; xr[4 * i + 3] = t.w;
    }
    float be = -3.4e38f;
    int bk = 0;
    #pragma unroll 1
    for (int k = 0; k < KCB; k++) {
        const float* vr = vq + (size_t)k * DIM;
        float a0 = 0.f, a1 = 0.f;
        #pragma unroll
        for (int d = 0; d < DIM; d += 2) {
            a0 = fmaf(xr[d],     __ldg(vr + d),     a0);
            a1 = fmaf(xr[d + 1], __ldg(vr + d + 1), a1);
        }
        float s = (a0 + a1) - sbias[k];
        if (s > be) { be = s; bk = k; }   // strict >: lowest k wins ties
    }
    return bk;
}

// ---------------- fused kernel ----------------
__global__ void __launch_bounds__(TPB, 1) vq_kernel(
    const float* __restrict__ x,
    const float* __restrict__ vq,
    const float* __restrict__ cs_in,
    const float* __restrict__ cn_in,
    float* __restrict__ q_out,
    float* __restrict__ vq_out,
    float* __restrict__ cs_out,
    float* __restrict__ cn_out)
{
    extern __shared__ __align__(1024) char smem[];
    float* sbias = reinterpret_cast<float*>(smem + SM_BIAS);
    const uint32_t sb = smem_u32(smem);
    const int tid = threadIdx.x;
    const int lane = tid & 31, wid = tid >> 5;
    const int g = lane >> 2, c = lane & 3;

    // ---- stage: split fp32 codebook -> fp16 hi/mid swizzled smem ----
    for (int i = tid; i < 4096; i += TPB) {   // 16B chunk i: row i>>3, cols (i&7)*8
        const float4* p = reinterpret_cast<const float4*>(vq + (i >> 3) * DIM + (i & 7) * 8);
        float4 v0 = __ldg(p), v1 = __ldg(p + 1);
        uint4 h4, m4;
        split2h(v0.x, v0.y, h4.x, m4.x);
        split2h(v0.z, v0.w, h4.y, m4.y);
        split2h(v1.x, v1.y, h4.z, m4.z);
        split2h(v1.z, v1.w, h4.w, m4.w);
        uint32_t off = SW((uint32_t)(i * 16));
        *reinterpret_cast<uint4*>(smem + SM_B_HI + off) = h4;
        *reinterpret_cast<uint4*>(smem + SM_B_MID + off) = m4;
    }
    // bias: 0.5*||v_k||^2 (exact fp32)
    for (int k = tid; k < KCB; k += TPB) {
        const float4* p = reinterpret_cast<const float4*>(vq + k * DIM);
        float s = 0.f;
        #pragma unroll
        for (int i = 0; i < DIM / 4; i++) {
            float4 t = __ldg(p + i);
            s += t.x * t.x + t.y * t.y + t.z * t.z + t.w * t.w;
        }
        sbias[k] = 0.5f * s;
    }

    // ---- A fragments: warp's 32 token rows x 64 dims, fp16 hi+mid ----
    uint32_t a_hi[2][4][4], a_mid[2][4][4];
    const int rowbase = blockIdx.x * TOK_CTA + wid * 32;
    #pragma unroll
    for (int m = 0; m < 2; m++) {
        #pragma unroll
        for (int kt = 0; kt < 4; kt++) {
            const float* p = x + (size_t)(rowbase + m * 16 + g) * DIM + kt * 16 + 2 * c;
            float2 f0 = *reinterpret_cast<const float2*>(p);
            float2 f1 = *reinterpret_cast<const float2*>(p + 8);
            float2 f2 = *reinterpret_cast<const float2*>(p + 8 * DIM);
            float2 f3 = *reinterpret_cast<const float2*>(p + 8 * DIM + 8);
            split2h(f0.x, f0.y, a_hi[m][kt][0], a_mid[m][kt][0]);
            split2h(f2.x, f2.y, a_hi[m][kt][1], a_mid[m][kt][1]);
            split2h(f1.x, f1.y, a_hi[m][kt][2], a_mid[m][kt][2]);
            split2h(f3.x, f3.y, a_hi[m][kt][3], a_mid[m][kt][3]);
        }
    }
    __syncthreads();

    float best[4]   = {-3.4e38f, -3.4e38f, -3.4e38f, -3.4e38f};
    float second[4] = {-3.4e38f, -3.4e38f, -3.4e38f, -3.4e38f};
    int   bk[4]     = {0, 0, 0, 0};

    // 64 blocks of 8 codewords; 6 independent accumulator chains
    #pragma unroll 1
    for (int nb = 0; nb < 64; nb++) {
        const int n0 = nb * 8;
        float Chh[2][4] = {}, Chm[2][4] = {}, Cmh[2][4] = {};
        #pragma unroll
        for (int kh = 0; kh < 2; kh++) {
            uint32_t off = SW((uint32_t)((n0 + (lane & 7)) * 128) + kh * 64 + ((lane >> 3) * 16));
            uint32_t bh[4], bm[4];
            LDMX4(bh, sb + SM_B_HI + off);
            LDMX4(bm, sb + SM_B_MID + off);
            #pragma unroll
            for (int kk = 0; kk < 2; kk++) {
                const int kt = kh * 2 + kk;
                #pragma unroll
                for (int m = 0; m < 2; m++) {
                    MMA(Chh[m], a_hi[m][kt],  bh[2 * kk], bh[2 * kk + 1]);
                    MMA(Chm[m], a_hi[m][kt],  bm[2 * kk], bm[2 * kk + 1]);
                    MMA(Cmh[m], a_mid[m][kt], bh[2 * kk], bh[2 * kk + 1]);
                }
            }
        }
        const int kA = n0 + 2 * c;
        float2 bias2 = *reinterpret_cast<const float2*>(&sbias[kA]);
        #pragma unroll
        for (int m = 0; m < 2; m++) {
            float s0 = Chh[m][0] + Chm[m][0] + Cmh[m][0] - bias2.x;
            float s1 = Chh[m][1] + Chm[m][1] + Cmh[m][1] - bias2.y;
            float s2 = Chh[m][2] + Chm[m][2] + Cmh[m][2] - bias2.x;
            float s3 = Chh[m][3] + Chm[m][3] + Cmh[m][3] - bias2.y;
            upd(s0, kA,     best[2 * m],     second[2 * m],     bk[2 * m]);
            upd(s1, kA + 1, best[2 * m],     second[2 * m],     bk[2 * m]);
            upd(s2, kA,     best[2 * m + 1], second[2 * m + 1], bk[2 * m + 1]);
            upd(s3, kA + 1, best[2 * m + 1], second[2 * m + 1], bk[2 * m + 1]);
        }
    }

    // ---- quad merge (cols spread over c=0..3) ----
    #pragma unroll
    for (int mask = 1; mask <= 2; mask <<= 1) {
        #pragma unroll
        for (int s = 0; s < 4; s++) {
            float ob = __shfl_xor_sync(0xffffffffu, best[s], mask);
            float os = __shfl_xor_sync(0xffffffffu, second[s], mask);
            int   ok = __shfl_xor_sync(0xffffffffu, bk[s], mask);
            if (ob > best[s]) {
                second[s] = fmaxf(best[s], fmaxf(os, second[s]));
                best[s] = ob; bk[s] = ok;
            } else {
                second[s] = fmaxf(second[s], fmaxf(os, ob));
            }
        }
    }
    // redistribute: thread with lane L takes slot L>>3 from lane 4*(L&7)
    float myBest = 0.f, mySecond = 0.f;
    int myK = 0;
    #pragma unroll
    for (int s = 0; s < 4; s++) {
        float b  = __shfl_sync(0xffffffffu, best[s],   (lane & 7) * 4);
        float sc = __shfl_sync(0xffffffffu, second[s], (lane & 7) * 4);
        int   kk = __shfl_sync(0xffffffffu, bk[s],     (lane & 7) * 4);
        if ((lane >> 3) == s) { myBest = b; mySecond = sc; myK = kk; }
    }

    // ---- epilogue (thread t <-> token t) ----
    const int tok = blockIdx.x * TOK_CTA + tid;
    int best_k = myK;
    if (mySecond >= myBest - MARGIN)
        best_k = rescue(x, vq, sbias, tok);

    {   // quantized = vq[best_k]
        const float4* vr4 = reinterpret_cast<const float4*>(vq + (size_t)best_k * DIM);
        float4* q4 = reinterpret_cast<float4*>(q_out + (size_t)tok * DIM);
        #pragma unroll
        for (int i = 0; i < DIM / 4; i++) q4[i] = vr4[i];
    }
    {   // segment sums (RED)
        const float4* xp = reinterpret_cast<const float4*>(x + (size_t)tok * DIM);
        float* cs = g_cs + (size_t)best_k * DIM;
        #pragma unroll
        for (int i = 0; i < DIM / 4; i++) {
            float4 v = xp[i];
            atomicAdd(cs + 4 * i,     v.x);
            atomicAdd(cs + 4 * i + 1, v.y);
            atomicAdd(cs + 4 * i + 2, v.z);
            atomicAdd(cs + 4 * i + 3, v.w);
        }
        atomicAdd(&g_cn[best_k], 1.0f);
    }

    // ---- last CTA performs the EMA finalize ----
    __threadfence();
    __syncthreads();
    __shared__ int s_last;
    if (tid == 0) s_last = (atomicAdd(&g_done, 1u) == (unsigned)(gridDim.x - 1));
    __syncthreads();
    if (!s_last) return;
    __threadfence();   // acquire: all CTAs' REDs visible

    float* scn = sbias + KCB;   // reuse smem scratch for cn_new
    for (int k = tid; k < KCB; k += TPB) {
        float cn_acc = g_cn[k];
        g_cn[k] = 0.f;
        float cn_new = cn_in[k] * GAMMA + cn_acc * (1.0f - GAMMA);
        cn_out[k] = cn_new;
        scn[k] = cn_new;
    }
    __syncthreads();
    for (int idx = tid; idx < KCB * DIM; idx += TPB) {
        float cs_acc = g_cs[idx];
        g_cs[idx] = 0.f;
        float cs_new = cs_in[idx] * GAMMA + cs_acc * (1.0f - GAMMA);
        cs_out[idx] = cs_new;
        vq_out[idx] = cs_new / scn[idx >> 6];
    }
    if (tid == 0) g_done = 0u;   // reset for next graph replay
}

extern "C" void kernel_launch(void* const* d_in, const int* in_sizes, int n_in,
                              void* d_out, int out_size) {
    const float* x  = (const float*)d_in[0];   // [N, 64]
    const float* vq = (const float*)d_in[1];   // [512, 64]
    const float* cs = (const float*)d_in[2];   // [512, 64]
    const float* cn = (const float*)d_in[3];   // [512]

    float* out    = (float*)d_out;
    float* q_out  = out;                        // [N, 64]
    float* vq_out = out + (size_t)N_TOK * DIM;  // [512, 64]
    float* cs_out = vq_out + (size_t)KCB * DIM; // [512, 64]
    float* cn_out = cs_out + (size_t)KCB * DIM; // [512]

    cudaFuncSetAttribute(vq_kernel, cudaFuncAttributeMaxDynamicSharedMemorySize, SMEM_BYTES);
    vq_kernel<<<NCTA, TPB, SMEM_BYTES>>>(x, vq, cs, cn, q_out, vq_out, cs_out, cn_out);
}

// round 8
// speedup vs baseline: 1.2596x; 1.2596x over previous
#include <cuda_runtime.h>
#include <cuda_fp16.h>
#include <cstdint>

// Problem constants
#define N_TOK 262144
#define DIM   64
#define KCB   512
#define GAMMA 0.99f

#define TPB     256
#define TOK_CTA 256
#define NCTA    (N_TOK / TOK_CTA)

// smem layout (bytes)
#define SM_B     0                       // 512x64 fp16, SW128 rows = 64KB (coarse B)
#define SM_BIAS  65536                   // 512 f32
#define SM_VT    67584                   // fp32 codebook TRANSPOSED [64][512] = 128KB
#define SMEM_BYTES (SM_VT + KCB * DIM * 4)   // 198656

#define SW(o) ((o) ^ (((o) >> 3) & 0x70))

// device globals (allocation-free; zero-init at load, self-rezeroing each call)
__device__ float g_cs[KCB * DIM];
__device__ float g_cn[KCB];
__device__ unsigned int g_done;

// ---------------- helpers ----------------
__device__ __forceinline__ uint32_t smem_u32(const void* p) {
    uint32_t a;
    asm("{ .reg .u64 t; cvta.to.shared.u64 t, %1; cvt.u32.u64 %0, t; }" : "=r"(a) : "l"(p));
    return a;
}
__device__ __forceinline__ uint32_t h2rn(float a, float b) {
    __half2 h = __floats2half2_rn(a, b);
    return *reinterpret_cast<uint32_t*>(&h);
}

#define LDMX4(R, A) \
    asm volatile("ldmatrix.sync.aligned.m8n8.x4.shared.b16 {%0,%1,%2,%3}, [%4];" \
                 : "=r"((R)[0]), "=r"((R)[1]), "=r"((R)[2]), "=r"((R)[3]) : "r"(A))

#define MMA(C, A, B0, B1) \
    asm volatile("mma.sync.aligned.m16n8k16.row.col.f32.f16.f16.f32 " \
                 "{%0,%1,%2,%3}, {%4,%5,%6,%7}, {%8,%9}, {%0,%1,%2,%3};" \
                 : "+f"((C)[0]), "+f"((C)[1]), "+f"((C)[2]), "+f"((C)[3]) \
                 : "r"((A)[0]), "r"((A)[1]), "r"((A)[2]), "r"((A)[3]), "r"(B0), "r"(B1))

__device__ __forceinline__ void upd(float v, int kk, float& best, float& second, int& bk) {
    if (v > best) { second = best; best = v; bk = kk; }
    else          { second = fmaxf(second, v); }
}

// ---------------- fused kernel ----------------
__global__ void __launch_bounds__(TPB) vq_kernel(
    const float* __restrict__ x,
    const float* __restrict__ vq,
    const float* __restrict__ cs_in,
    const float* __restrict__ cn_in,
    float* __restrict__ q_out,
    float* __restrict__ vq_out,
    float* __restrict__ cs_out,
    float* __restrict__ cn_out)
{
    extern __shared__ __align__(1024) char smem[];
    float* sbias = reinterpret_cast<float*>(smem + SM_BIAS);
    float* VT    = reinterpret_cast<float*>(smem + SM_VT);
    const uint32_t sb = smem_u32(smem);
    const int tid = threadIdx.x;
    const int lane = tid & 31, wid = tid >> 5;
    const int g = lane >> 2, c = lane & 3;

    // ---- stage 1: fp32 codebook -> fp16 (RN) swizzled smem (coarse B) ----
    for (int i = tid; i < 4096; i += TPB) {   // 16B fp16 chunk: row i>>3, cols (i&7)*8
        const float4* p = reinterpret_cast<const float4*>(vq + (i >> 3) * DIM + (i & 7) * 8);
        float4 v0 = __ldg(p), v1 = __ldg(p + 1);
        uint4 h4;
        h4.x = h2rn(v0.x, v0.y); h4.y = h2rn(v0.z, v0.w);
        h4.z = h2rn(v1.x, v1.y); h4.w = h2rn(v1.z, v1.w);
        *reinterpret_cast<uint4*>(smem + SM_B + SW((uint32_t)(i * 16))) = h4;
    }
    // ---- stage 2: transposed fp32 codebook VT[d][k] (rescue source) ----
    for (int i = tid; i < 8192; i += TPB) {   // float4 i: codeword k=i&511, d4=i>>9
        int k = i & 511, d4 = i >> 9;
        float4 v = __ldg(reinterpret_cast<const float4*>(vq + k * DIM + d4 * 4));
        float* col = VT + d4 * 4 * KCB + k;
        col[0] = v.x; col[KCB] = v.y; col[2 * KCB] = v.z; col[3 * KCB] = v.w;
    }
    // ---- stage 3: bias 0.5*||v_k||^2 (exact fp32) ----
    for (int k = tid; k < KCB; k += TPB) {
        const float4* p = reinterpret_cast<const float4*>(vq + k * DIM);
        float s = 0.f;
        #pragma unroll
        for (int i = 0; i < DIM / 4; i++) {
            float4 t = __ldg(p + i);
            s += t.x * t.x + t.y * t.y + t.z * t.z + t.w * t.w;
        }
        sbias[k] = 0.5f * s;
    }

    // ---- A fragments: warp's 32 token rows x 64 dims, fp16 RN ----
    uint32_t a_f[2][4][4];
    const int rowbase = blockIdx.x * TOK_CTA + wid * 32;
    #pragma unroll
    for (int m = 0; m < 2; m++) {
        #pragma unroll
        for (int kt = 0; kt < 4; kt++) {
            const float* p = x + (size_t)(rowbase + m * 16 + g) * DIM + kt * 16 + 2 * c;
            float2 f0 = *reinterpret_cast<const float2*>(p);
            float2 f1 = *reinterpret_cast<const float2*>(p + 8);
            float2 f2 = *reinterpret_cast<const float2*>(p + 8 * DIM);
            float2 f3 = *reinterpret_cast<const float2*>(p + 8 * DIM + 8);
            a_f[m][kt][0] = h2rn(f0.x, f0.y);
            a_f[m][kt][1] = h2rn(f2.x, f2.y);
            a_f[m][kt][2] = h2rn(f1.x, f1.y);
            a_f[m][kt][3] = h2rn(f3.x, f3.y);
        }
    }
    __syncthreads();

    // ---- per-warp Vmax = max_k ||v_k|| (registers only) ----
    float vmax;
    {
        float vm = 0.f;
        #pragma unroll
        for (int j = 0; j < KCB / 32; j++) vm = fmaxf(vm, sbias[lane + 32 * j]);
        #pragma unroll
        for (int o = 16; o; o >>= 1) vm = fmaxf(vm, __shfl_xor_sync(0xffffffffu, vm, o));
        vmax = sqrtf(2.f * vm);
    }

    float best[4]   = {-3.4e38f, -3.4e38f, -3.4e38f, -3.4e38f};
    float second[4] = {-3.4e38f, -3.4e38f, -3.4e38f, -3.4e38f};
    int   bk[4]     = {0, 0, 0, 0};

    // ---- coarse: 64 blocks of 8 codewords, single fp16 GEMM term ----
    #pragma unroll 1
    for (int nb = 0; nb < 64; nb++) {
        const int n0 = nb * 8;
        float C[2][4] = {};
        #pragma unroll
        for (int kh = 0; kh < 2; kh++) {
            uint32_t off = SW((uint32_t)((n0 + (lane & 7)) * 128) + kh * 64 + ((lane >> 3) * 16));
            uint32_t b[4];
            LDMX4(b, sb + SM_B + off);
            #pragma unroll
            for (int kk = 0; kk < 2; kk++) {
                const int kt = kh * 2 + kk;
                MMA(C[0], a_f[0][kt], b[2 * kk], b[2 * kk + 1]);
                MMA(C[1], a_f[1][kt], b[2 * kk], b[2 * kk + 1]);
            }
        }
        const int kA = n0 + 2 * c;
        float2 b2 = *reinterpret_cast<const float2*>(&sbias[kA]);
        #pragma unroll
        for (int m = 0; m < 2; m++) {
            upd(C[m][0] - b2.x, kA,     best[2 * m],     second[2 * m],     bk[2 * m]);
            upd(C[m][1] - b2.y, kA + 1, best[2 * m],     second[2 * m],     bk[2 * m]);
            upd(C[m][2] - b2.x, kA,     best[2 * m + 1], second[2 * m + 1], bk[2 * m + 1]);
            upd(C[m][3] - b2.y, kA + 1, best[2 * m + 1], second[2 * m + 1], bk[2 * m + 1]);
        }
    }

    // ---- quad merge (cols spread over c=0..3) ----
    #pragma unroll
    for (int mask = 1; mask <= 2; mask <<= 1) {
        #pragma unroll
        for (int s = 0; s < 4; s++) {
            float ob = __shfl_xor_sync(0xffffffffu, best[s], mask);
            float os = __shfl_xor_sync(0xffffffffu, second[s], mask);
            int   ok = __shfl_xor_sync(0xffffffffu, bk[s], mask);
            if (ob > best[s]) {
                second[s] = fmaxf(best[s], fmaxf(os, second[s]));
                best[s] = ob; bk[s] = ok;
            } else {
                second[s] = fmaxf(second[s], fmaxf(os, ob));
            }
        }
    }
    // redistribute: lane L takes slot L>>3 from lane 4*(L&7)
    float myBest = 0.f, mySecond = 0.f;
    int myK = 0;
    #pragma unroll
    for (int s = 0; s < 4; s++) {
        float b  = __shfl_sync(0xffffffffu, best[s],   (lane & 7) * 4);
        float sc = __shfl_sync(0xffffffffu, second[s], (lane & 7) * 4);
        int   kk = __shfl_sync(0xffffffffu, bk[s],     (lane & 7) * 4);
        if ((lane >> 3) == s) { myBest = b; mySecond = sc; myK = kk; }
    }

    // ---- margin check (thread t <-> token t), FULL 64-dim x row ----
    const int tok = blockIdx.x * TOK_CTA + tid;
    float4 xr4[16];
    {
        const float4* xp = reinterpret_cast<const float4*>(x + (size_t)tok * DIM);
        #pragma unroll
        for (int i = 0; i < 16; i++) xr4[i] = xp[i];
    }
    float xn2 = 0.f;
    #pragma unroll
    for (int i = 0; i < 16; i++)
        xn2 += xr4[i].x * xr4[i].x + xr4[i].y * xr4[i].y + xr4[i].z * xr4[i].z + xr4[i].w * xr4[i].w;
    // fp16-RN score error <= 2*2^-11*||x||*||v|| per score, x2 pairwise, + accum slack
    const float marg = 2.2e-3f * sqrtf(xn2) * vmax + 2e-4f;

    // ---- ballot rescue: whole warp rescores each ambiguous lane's token ----
    int best_k = myK;
    {
        unsigned rmask = __ballot_sync(0xffffffffu, mySecond >= myBest - marg);
        while (rmask) {
            const int src = __ffs(rmask) - 1;
            rmask &= rmask - 1;
            float acc[16];
            #pragma unroll
            for (int kk = 0; kk < 16; kk++) acc[kk] = 0.f;
            #pragma unroll
            for (int cch = 0; cch < 4; cch++) {      // 4 chunks of 16 dims
                float xs16[16];
                #pragma unroll
                for (int i = 0; i < 4; i++) {
                    xs16[4 * i]     = __shfl_sync(0xffffffffu, xr4[4 * cch + i].x, src);
                    xs16[4 * i + 1] = __shfl_sync(0xffffffffu, xr4[4 * cch + i].y, src);
                    xs16[4 * i + 2] = __shfl_sync(0xffffffffu, xr4[4 * cch + i].z, src);
                    xs16[4 * i + 3] = __shfl_sync(0xffffffffu, xr4[4 * cch + i].w, src);
                }
                #pragma unroll
                for (int dd = 0; dd < 16; dd++) {
                    const float xd = xs16[dd];
                    const float* row = VT + (16 * cch + dd) * KCB + lane;
                    #pragma unroll
                    for (int kk = 0; kk < 16; kk++)
                        acc[kk] = fmaf(xd, row[32 * kk], acc[kk]);
                }
            }
            float be = -3.4e38f;
            int bkk = 0;
            #pragma unroll
            for (int kk = 0; kk < 16; kk++) {
                int k = lane + 32 * kk;
                float s = acc[kk] - sbias[k];
                if (s > be) { be = s; bkk = k; }
            }
            #pragma unroll
            for (int o = 16; o; o >>= 1) {
                float ob = __shfl_xor_sync(0xffffffffu, be, o);
                int   ok = __shfl_xor_sync(0xffffffffu, bkk, o);
                if (ob > be || (ob == be && ok < bkk)) { be = ob; bkk = ok; }
            }
            if (lane == src) best_k = bkk;
        }
    }

    // ---- gather (full row!) + segment sums ----
    {
        const float4* vr4 = reinterpret_cast<const float4*>(vq + (size_t)best_k * DIM);
        float4* q4 = reinterpret_cast<float4*>(q_out + (size_t)tok * DIM);
        #pragma unroll
        for (int i = 0; i < 16; i++) q4[i] = vr4[i];
    }
    {
        float* cs = g_cs + (size_t)best_k * DIM;
        #pragma unroll
        for (int i = 0; i < 16; i++) {
            atomicAdd(cs + 4 * i,     xr4[i].x);
            atomicAdd(cs + 4 * i + 1, xr4[i].y);
            atomicAdd(cs + 4 * i + 2, xr4[i].z);
            atomicAdd(cs + 4 * i + 3, xr4[i].w);
        }
        atomicAdd(&g_cn[best_k], 1.0f);
    }

    // ---- last CTA performs the EMA finalize ----
    __threadfence();
    __syncthreads();
    __shared__ int s_last;
    if (tid == 0) s_last = (atomicAdd(&g_done, 1u) == (unsigned)(gridDim.x - 1));
    __syncthreads();
    if (!s_last) return;
    __threadfence();   // acquire: all CTAs' REDs visible

    float* scn = reinterpret_cast<float*>(smem);   // coarse B area done
    for (int k = tid; k < KCB; k += TPB) {
        float cn_acc = g_cn[k];
        g_cn[k] = 0.f;
        float cn_new = cn_in[k] * GAMMA + cn_acc * (1.0f - GAMMA);
        cn_out[k] = cn_new;
        scn[k] = cn_new;
    }
    __syncthreads();
    for (int idx = tid; idx < KCB * DIM; idx += TPB) {
        float cs_acc = g_cs[idx];
        g_cs[idx] = 0.f;
        float cs_new = cs_in[idx] * GAMMA + cs_acc * (1.0f - GAMMA);
        cs_out[idx] = cs_new;
        vq_out[idx] = cs_new / scn[idx >> 6];
    }
    if (tid == 0) g_done = 0u;   // reset for next graph replay
}

extern "C" void kernel_launch(void* const* d_in, const int* in_sizes, int n_in,
                              void* d_out, int out_size) {
    const float* x  = (const float*)d_in[0];   // [N, 64]
    const float* vq = (const float*)d_in[1];   // [512, 64]
    const float* cs = (const float*)d_in[2];   // [512, 64]
    const float* cn = (const float*)d_in[3];   // [512]

    float* out    = (float*)d_out;
    float* q_out  = out;                        // [N, 64]
    float* vq_out = out + (size_t)N_TOK * DIM;  // [512, 64]
    float* cs_out = vq_out + (size_t)KCB * DIM; // [512, 64]
    float* cn_out = cs_out + (size_t)KCB * DIM; // [512]

    cudaFuncSetAttribute(vq_kernel, cudaFuncAttributeMaxDynamicSharedMemorySize, SMEM_BYTES);
    vq_kernel<<<NCTA, TPB, SMEM_BYTES>>>(x, vq, cs, cn, q_out, vq_out, cs_out, cn_out);
}

// round 9
// speedup vs baseline: 2.3041x; 1.8292x over previous
#include <cuda_runtime.h>
#include <cuda_fp16.h>
#include <cstdint>

// Problem constants
#define N_TOK 262144
#define DIM   64
#define KCB   512
#define GAMMA 0.99f

#define TPB     256
#define TOK_CTA 256
#define NCTA    (N_TOK / TOK_CTA)

// smem layout (bytes): fp16 codebook (SW128) | bias | per-warp midnorm slots
#define SM_B     0                     // 512x64 fp16 = 64KB
#define SM_BIAS  65536                 // 512 f32
#define SM_WMAX  (SM_BIAS + 2048)      // 8 f32
#define SMEM_BYTES (SM_WMAX + 64)

#define SW(o) ((o) ^ (((o) >> 3) & 0x70))

// device globals (zero-init at load; self-rezeroing each call)
__device__ float g_cs[KCB * DIM];
__device__ float g_cn[KCB];
__device__ unsigned int g_done;

// ---------------- helpers ----------------
__device__ __forceinline__ uint32_t smem_u32(const void* p) {
    uint32_t a;
    asm("{ .reg .u64 t; cvta.to.shared.u64 t, %1; cvt.u32.u64 %0, t; }" : "=r"(a) : "l"(p));
    return a;
}
__device__ __forceinline__ uint32_t h2rn(float a, float b) {
    __half2 h = __floats2half2_rn(a, b);
    return *reinterpret_cast<uint32_t*>(&h);
}
__device__ __forceinline__ float2 h2back(uint32_t u) {
    return __half22float2(*reinterpret_cast<__half2*>(&u));
}
__device__ __forceinline__ void red4(float* dst, float4 v) {
    asm volatile("red.global.add.v4.f32 [%0], {%1,%2,%3,%4};"
                 :: "l"(dst), "f"(v.x), "f"(v.y), "f"(v.z), "f"(v.w) : "memory");
}

#define LDMX4(R, A) \
    asm volatile("ldmatrix.sync.aligned.m8n8.x4.shared.b16 {%0,%1,%2,%3}, [%4];" \
                 : "=r"((R)[0]), "=r"((R)[1]), "=r"((R)[2]), "=r"((R)[3]) : "r"(A))

#define MMA(C, A, B0, B1) \
    asm volatile("mma.sync.aligned.m16n8k16.row.col.f32.f16.f16.f32 " \
                 "{%0,%1,%2,%3}, {%4,%5,%6,%7}, {%8,%9}, {%0,%1,%2,%3};" \
                 : "+f"((C)[0]), "+f"((C)[1]), "+f"((C)[2]), "+f"((C)[3]) \
                 : "r"((A)[0]), "r"((A)[1]), "r"((A)[2]), "r"((A)[3]), "r"(B0), "r"(B1))

// top-3 values + top-2 indices
__device__ __forceinline__ void upd3(float v, int kk, float& b, float& s, float& t,
                                     int& k1, int& k2) {
    if (v > t) {
        if (v > b)      { t = s; s = b; k2 = k1; b = v; k1 = kk; }
        else if (v > s) { t = s; s = v; k2 = kk; }
        else            { t = v; }
    }
}

// ---------------- fused kernel ----------------
__global__ void __launch_bounds__(TPB) vq_kernel(
    const float* __restrict__ x,
    const float* __restrict__ vq,
    const float* __restrict__ cs_in,
    const float* __restrict__ cn_in,
    float* __restrict__ q_out,
    float* __restrict__ vq_out,
    float* __restrict__ cs_out,
    float* __restrict__ cn_out)
{
    extern __shared__ __align__(1024) char smem[];
    float* sbias = reinterpret_cast<float*>(smem + SM_BIAS);
    float* swmax = reinterpret_cast<float*>(smem + SM_WMAX);
    const uint32_t sb = smem_u32(smem);
    const int tid = threadIdx.x;
    const int lane = tid & 31, wid = tid >> 5;
    const int g = lane >> 2, c = lane & 3;

    // ---- stage: codebook -> fp16 smem + exact bias + mid-norm max (coalesced) ----
    {
        float wvm = 0.f;
        #pragma unroll 1
        for (int it = 0; it < 16; it++) {
            int i = tid + TPB * it;                 // chunk: row i>>3, cols (i&7)*8
            const float4* p = reinterpret_cast<const float4*>(vq + (i >> 3) * DIM + (i & 7) * 8);
            float4 v0 = __ldg(p), v1 = __ldg(p + 1);
            uint4 h4;
            h4.x = h2rn(v0.x, v0.y); h4.y = h2rn(v0.z, v0.w);
            h4.z = h2rn(v1.x, v1.y); h4.w = h2rn(v1.z, v1.w);
            *reinterpret_cast<uint4*>(smem + SM_B + SW((uint32_t)(i * 16))) = h4;
            // exact ||v||^2 and ||v_mid||^2 partials (8 dims)
            float2 b0 = h2back(h4.x), b1 = h2back(h4.y), b2 = h2back(h4.z), b3 = h2back(h4.w);
            float bb = v0.x * v0.x + v0.y * v0.y + v0.z * v0.z + v0.w * v0.w
                     + v1.x * v1.x + v1.y * v1.y + v1.z * v1.z + v1.w * v1.w;
            float m0 = v0.x - b0.x, m1 = v0.y - b0.y, m2 = v0.z - b1.x, m3 = v0.w - b1.y;
            float m4 = v1.x - b2.x, m5 = v1.y - b2.y, m6 = v1.z - b3.x, m7 = v1.w - b3.y;
            float nm = m0 * m0 + m1 * m1 + m2 * m2 + m3 * m3
                     + m4 * m4 + m5 * m5 + m6 * m6 + m7 * m7;
            #pragma unroll
            for (int o = 1; o < 8; o <<= 1) {       // 8-lane row reduce
                bb += __shfl_xor_sync(0xffffffffu, bb, o);
                nm += __shfl_xor_sync(0xffffffffu, nm, o);
            }
            if ((tid & 7) == 0) sbias[i >> 3] = 0.5f * bb;
            wvm = fmaxf(wvm, nm);
        }
        #pragma unroll
        for (int o = 8; o < 32; o <<= 1) wvm = fmaxf(wvm, __shfl_xor_sync(0xffffffffu, wvm, o));
        if (lane == 0) swmax[wid] = wvm;
    }

    // ---- A fragments + per-slot hi/mid norms ----
    uint32_t a_f[2][4][4];
    float nh2p[4] = {0.f, 0.f, 0.f, 0.f}, nm2p[4] = {0.f, 0.f, 0.f, 0.f};
    const int rowbase = blockIdx.x * TOK_CTA + wid * 32;
    #pragma unroll
    for (int m = 0; m < 2; m++) {
        #pragma unroll
        for (int kt = 0; kt < 4; kt++) {
            const float* p = x + (size_t)(rowbase + m * 16 + g) * DIM + kt * 16 + 2 * c;
            float2 f0 = *reinterpret_cast<const float2*>(p);
            float2 f1 = *reinterpret_cast<const float2*>(p + 8);
            float2 f2 = *reinterpret_cast<const float2*>(p + 8 * DIM);
            float2 f3 = *reinterpret_cast<const float2*>(p + 8 * DIM + 8);
            a_f[m][kt][0] = h2rn(f0.x, f0.y);
            a_f[m][kt][1] = h2rn(f2.x, f2.y);
            a_f[m][kt][2] = h2rn(f1.x, f1.y);
            a_f[m][kt][3] = h2rn(f3.x, f3.y);
            float2 h0 = h2back(a_f[m][kt][0]), h1 = h2back(a_f[m][kt][1]);
            float2 h2 = h2back(a_f[m][kt][2]), h3 = h2back(a_f[m][kt][3]);
            // slot 2m: rows 16m+g (f0,f1); slot 2m+1: rows 16m+8+g (f2,f3)
            nh2p[2 * m]     += h0.x * h0.x + h0.y * h0.y + h2.x * h2.x + h2.y * h2.y;
            nh2p[2 * m + 1] += h1.x * h1.x + h1.y * h1.y + h3.x * h3.x + h3.y * h3.y;
            float a0 = f0.x - h0.x, a1 = f0.y - h0.y, a2 = f1.x - h2.x, a3 = f1.y - h2.y;
            float b0 = f2.x - h1.x, b1 = f2.y - h1.y, b2 = f3.x - h3.x, b3 = f3.y - h3.y;
            nm2p[2 * m]     += a0 * a0 + a1 * a1 + a2 * a2 + a3 * a3;
            nm2p[2 * m + 1] += b0 * b0 + b1 * b1 + b2 * b2 + b3 * b3;
        }
    }
    #pragma unroll
    for (int o = 1; o <= 2; o <<= 1) {   // quad reduce norms over c
        #pragma unroll
        for (int s = 0; s < 4; s++) {
            nh2p[s] += __shfl_xor_sync(0xffffffffu, nh2p[s], o);
            nm2p[s] += __shfl_xor_sync(0xffffffffu, nm2p[s], o);
        }
    }
    __syncthreads();

    // vmax and vmidmax
    float vmax, vmidmax;
    {
        float vm = 0.f;
        #pragma unroll
        for (int j = 0; j < KCB / 32; j++) vm = fmaxf(vm, sbias[lane + 32 * j]);
        #pragma unroll
        for (int o = 16; o; o >>= 1) vm = fmaxf(vm, __shfl_xor_sync(0xffffffffu, vm, o));
        vmax = sqrtf(2.f * vm);
        float wm = 0.f;
        #pragma unroll
        for (int j = 0; j < 8; j++) wm = fmaxf(wm, swmax[j]);
        vmidmax = sqrtf(wm);
    }

    float b3v[4], s3v[4], t3v[4];
    int k1v[4], k2v[4];
    #pragma unroll
    for (int s = 0; s < 4; s++) {
        b3v[s] = -3.4e38f; s3v[s] = -3.4e38f; t3v[s] = -3.4e38f; k1v[s] = 0; k2v[s] = 0;
    }

    // ---- coarse: 64 blocks of 8 codewords, single fp16 GEMM term ----
    #pragma unroll 1
    for (int nb = 0; nb < 64; nb++) {
        const int n0 = nb * 8;
        float C[2][4] = {};
        #pragma unroll
        for (int kh = 0; kh < 2; kh++) {
            uint32_t off = SW((uint32_t)((n0 + (lane & 7)) * 128) + kh * 64 + ((lane >> 3) * 16));
            uint32_t b[4];
            LDMX4(b, sb + SM_B + off);
            #pragma unroll
            for (int kk = 0; kk < 2; kk++) {
                const int kt = kh * 2 + kk;
                MMA(C[0], a_f[0][kt], b[2 * kk], b[2 * kk + 1]);
                MMA(C[1], a_f[1][kt], b[2 * kk], b[2 * kk + 1]);
            }
        }
        const int kA = n0 + 2 * c;
        float2 b2 = *reinterpret_cast<const float2*>(&sbias[kA]);
        #pragma unroll
        for (int m = 0; m < 2; m++) {
            upd3(C[m][0] - b2.x, kA,     b3v[2*m],   s3v[2*m],   t3v[2*m],   k1v[2*m],   k2v[2*m]);
            upd3(C[m][1] - b2.y, kA + 1, b3v[2*m],   s3v[2*m],   t3v[2*m],   k1v[2*m],   k2v[2*m]);
            upd3(C[m][2] - b2.x, kA,     b3v[2*m+1], s3v[2*m+1], t3v[2*m+1], k1v[2*m+1], k2v[2*m+1]);
            upd3(C[m][3] - b2.y, kA + 1, b3v[2*m+1], s3v[2*m+1], t3v[2*m+1], k1v[2*m+1], k2v[2*m+1]);
        }
    }

    // ---- quad merge of top-3 (over c=0..3) ----
    #pragma unroll
    for (int mask = 1; mask <= 2; mask <<= 1) {
        #pragma unroll
        for (int s = 0; s < 4; s++) {
            float ob = __shfl_xor_sync(0xffffffffu, b3v[s], mask);
            float os = __shfl_xor_sync(0xffffffffu, s3v[s], mask);
            float ot = __shfl_xor_sync(0xffffffffu, t3v[s], mask);
            int   ok1 = __shfl_xor_sync(0xffffffffu, k1v[s], mask);
            int   ok2 = __shfl_xor_sync(0xffffffffu, k2v[s], mask);
            if (ob > b3v[s]) {
                if (b3v[s] > os) { t3v[s] = fmaxf(s3v[s], os); s3v[s] = b3v[s]; k2v[s] = k1v[s]; }
                else             { t3v[s] = fmaxf(b3v[s], ot); s3v[s] = os;     k2v[s] = ok2; }
                b3v[s] = ob; k1v[s] = ok1;
            } else {
                if (ob > s3v[s]) { t3v[s] = fmaxf(s3v[s], os); s3v[s] = ob; k2v[s] = ok1; }
                else             { t3v[s] = fmaxf(t3v[s], ob); }
            }
        }
    }
    // redistribute: lane L (token row L) takes slot L>>3 from lane (L&7)*4
    float myB = 0.f, myS = 0.f, myT = 0.f, myNh2 = 0.f, myNm2 = 0.f;
    int myK1 = 0, myK2 = 0;
    #pragma unroll
    for (int s = 0; s < 4; s++) {
        const int srcl = (lane & 7) * 4;
        float vb = __shfl_sync(0xffffffffu, b3v[s], srcl);
        float vs = __shfl_sync(0xffffffffu, s3v[s], srcl);
        float vt = __shfl_sync(0xffffffffu, t3v[s], srcl);
        int   i1 = __shfl_sync(0xffffffffu, k1v[s], srcl);
        int   i2 = __shfl_sync(0xffffffffu, k2v[s], srcl);
        float nh = __shfl_sync(0xffffffffu, nh2p[s], srcl);
        float nm = __shfl_sync(0xffffffffu, nm2p[s], srcl);
        if ((lane >> 3) == s) {
            myB = vb; myS = vs; myT = vt; myK1 = i1; myK2 = i2; myNh2 = nh; myNm2 = nm;
        }
    }

    // ---- rigorous margin + tiered rescue ----
    const int tok = blockIdx.x * TOK_CTA + tid;
    const float nh = sqrtf(myNh2), nm = sqrtf(myNm2);
    const float marg = nm * vmax + nh * (vmidmax + 4e-6f * vmax) + 1e-6f;

    int best_k = myK1;
    bool fullf = false;
    if (myS >= myB - 2.f * marg) {
        // exact fp32 pair rescore (k1, k2)
        const float4* xp = reinterpret_cast<const float4*>(x + (size_t)tok * DIM);
        const float4* va = reinterpret_cast<const float4*>(vq + (size_t)myK1 * DIM);
        const float4* vb = reinterpret_cast<const float4*>(vq + (size_t)myK2 * DIM);
        float e1 = 0.f, e2 = 0.f;
        #pragma unroll
        for (int i = 0; i < 16; i++) {
            float4 xv = __ldg(xp + i), u = __ldg(va + i), w = __ldg(vb + i);
            e1 = fmaf(xv.x, u.x, fmaf(xv.y, u.y, fmaf(xv.z, u.z, fmaf(xv.w, u.w, e1))));
            e2 = fmaf(xv.x, w.x, fmaf(xv.y, w.y, fmaf(xv.z, w.z, fmaf(xv.w, w.w, e2))));
        }
        e1 -= sbias[myK1];
        e2 -= sbias[myK2];
        float emax = fmaxf(e1, e2);
        int km = (e2 > e1) ? myK2 : ((e1 > e2) ? myK1 : min(myK1, myK2));
        if (emax >= myT + marg + 1e-4f) best_k = km;
        else fullf = true;
    }
    // cooperative coalesced full rescan (rare)
    {
        unsigned rm = __ballot_sync(0xffffffffu, fullf);
        const int cc = lane & 15, hg = lane >> 4;
        while (rm) {
            const int src = __ffs(rm) - 1;
            rm &= rm - 1;
            const int stok = blockIdx.x * TOK_CTA + wid * 32 + src;
            float4 xv = __ldg(reinterpret_cast<const float4*>(x + (size_t)stok * DIM) + cc);
            float be = -3.4e38f;
            int bkk = 0;
            #pragma unroll 1
            for (int p2 = 0; p2 < KCB / 2; p2++) {
                const int r = 2 * p2 + hg;
                float4 v = __ldg(reinterpret_cast<const float4*>(vq + (size_t)r * DIM) + cc);
                float d = fmaf(xv.x, v.x, fmaf(xv.y, v.y, fmaf(xv.z, v.z, xv.w * v.w)));
                #pragma unroll
                for (int o = 1; o < 16; o <<= 1) d += __shfl_xor_sync(0xffffffffu, d, o);
                d -= sbias[r];
                if (d > be) { be = d; bkk = r; }
            }
            float ob = __shfl_xor_sync(0xffffffffu, be, 16);
            int   ok = __shfl_xor_sync(0xffffffffu, bkk, 16);
            if (ob > be || (ob == be && ok < bkk)) { be = ob; bkk = ok; }
            if (lane == src) best_k = bkk;
        }
    }

    // ---- cooperative epilogue: gather + vector-RED segment sums ----
    {
        const int cc = lane & 15;
        #pragma unroll 1
        for (int p2 = 0; p2 < 16; p2++) {
            const int j = 2 * p2 + (lane >> 4);                 // token within warp
            const int kk = __shfl_sync(0xffffffffu, best_k, j);
            const int gt = blockIdx.x * TOK_CTA + wid * 32 + j; // global token
            float4 v = __ldg(reinterpret_cast<const float4*>(vq + (size_t)kk * DIM) + cc);
            reinterpret_cast<float4*>(q_out + (size_t)gt * DIM)[cc] = v;
            float4 xv = __ldg(reinterpret_cast<const float4*>(x + (size_t)gt * DIM) + cc);
            red4(g_cs + (size_t)kk * DIM + cc * 4, xv);
            if (cc == 0) atomicAdd(&g_cn[kk], 1.0f);
        }
    }

    // ---- last CTA performs the EMA finalize ----
    __threadfence();
    __syncthreads();
    __shared__ int s_last;
    if (tid == 0) s_last = (atomicAdd(&g_done, 1u) == (unsigned)(gridDim.x - 1));
    __syncthreads();
    if (!s_last) return;
    __threadfence();   // acquire: all CTAs' REDs visible

    float* scn = reinterpret_cast<float*>(smem);   // reuse codebook area
    for (int k = tid; k < KCB; k += TPB) {
        float cn_acc = g_cn[k];
        g_cn[k] = 0.f;
        float cn_new = cn_in[k] * GAMMA + cn_acc * (1.0f - GAMMA);
        cn_out[k] = cn_new;
        scn[k] = cn_new;
    }
    __syncthreads();
    for (int idx = tid; idx < KCB * DIM; idx += TPB) {
        float cs_acc = g_cs[idx];
        g_cs[idx] = 0.f;
        float cs_new = cs_in[idx] * GAMMA + cs_acc * (1.0f - GAMMA);
        cs_out[idx] = cs_new;
        vq_out[idx] = cs_new / scn[idx >> 6];
    }
    if (tid == 0) g_done = 0u;   // reset for next graph replay
}

extern "C" void kernel_launch(void* const* d_in, const int* in_sizes, int n_in,
                              void* d_out, int out_size) {
    const float* x  = (const float*)d_in[0];   // [N, 64]
    const float* vq = (const float*)d_in[1];   // [512, 64]
    const float* cs = (const float*)d_in[2];   // [512, 64]
    const float* cn = (const float*)d_in[3];   // [512]

    float* out    = (float*)d_out;
    float* q_out  = out;                        // [N, 64]
    float* vq_out = out + (size_t)N_TOK * DIM;  // [512, 64]
    float* cs_out = vq_out + (size_t)KCB * DIM; // [512, 64]
    float* cn_out = cs_out + (size_t)KCB * DIM; // [512]

    cudaFuncSetAttribute(vq_kernel, cudaFuncAttributeMaxDynamicSharedMemorySize, SMEM_BYTES);
    vq_kernel<<<NCTA, TPB, SMEM_BYTES>>>(x, vq, cs, cn, q_out, vq_out, cs_out, cn_out);
}